// round 3
// baseline (speedup 1.0000x reference)
#include <cuda_runtime.h>
#include <math_constants.h>

#define NB   8
#define NC   3
#define NN   4096
#define KK   10
#define TPB  512          // threads per block (2 per query)
#define QPB  256          // queries per block
#define MLP0 64
#define MLP1 64

// dynamic smem layout:
//   float4 cand[4096]          : 65536 B
//   float  w1eff[64*30]        :  7680 B
//   float  wfold[64*30]        :  7680 B
//   float  biasf[64]           :   256 B
#define SMEM_BYTES (NN*16 + MLP0*30*4 + MLP1*30*4 + MLP1*4)

__global__ __launch_bounds__(TPB, 1)
void pcms_kernel(const float* __restrict__ pos,
                 const float* __restrict__ w1,
                 const float* __restrict__ b1,
                 const float* __restrict__ w2,
                 const float* __restrict__ b2,
                 float* __restrict__ out)
{
    extern __shared__ float smem[];
    float4* cand  = reinterpret_cast<float4*>(smem);
    float*  w1eff = smem + NN * 4;
    float*  wfold = w1eff + MLP0 * 30;
    float*  biasf = wfold + MLP1 * 30;

    const int tid = threadIdx.x;
    const int b   = blockIdx.x >> 4;          // 16 chunks per batch
    const int n0  = (blockIdx.x & 15) * QPB;

    // ---- stage 0a: candidate table (x, y, z, 0.5*|p|^2) ----
    const float* pb = pos + b * (NC * NN);
    #pragma unroll
    for (int i = 0; i < NN / TPB; ++i) {
        int n = tid + i * TPB;
        float x = pb[n];
        float y = pb[NN + n];
        float z = pb[2 * NN + n];
        cand[n] = make_float4(x, y, z, 0.5f * (x * x + y * y + z * z));
    }

    // ---- stage 0b: fold w1 over the INDS/squeeze mapping -> w1eff[o][r*3+c] ----
    if (tid < MLP0) {
        float acc[30];
        #pragma unroll
        for (int i = 0; i < 30; ++i) acc[i] = 0.f;
        const int STAB[4][2][2] = {
            {{0, 2}, {4, 6}},   // a: (2i,   2j  )
            {{3, 5}, {7, 9}},   // d: (2i+1, 2j+1)
            {{1, 3}, {5, 7}},   // b: (2i,   2j+1)
            {{2, 4}, {6, 8}}    // c: (2i+1, 2j  )
        };
        #pragma unroll
        for (int q = 0; q < 4; ++q)
            #pragma unroll
            for (int c = 0; c < 3; ++c)
                #pragma unroll
                for (int i = 0; i < 2; ++i)
                    #pragma unroll
                    for (int j = 0; j < 2; ++j) {
                        int r = STAB[q][i][j];
                        acc[r * 3 + c] += w1[tid * 48 + (q * 3 + c) * 4 + i * 2 + j];
                    }
        #pragma unroll
        for (int i = 0; i < 30; ++i) w1eff[tid * 30 + i] = acc[i];
    }
    __syncthreads();

    // ---- stage 0c: wfold[p][rc] = sum_o w2[p][o] * w1eff[o][rc]; bias fold ----
    for (int e = tid; e < MLP1 * 30; e += TPB) {
        int p = e / 30, rc = e % 30;
        float s = 0.f;
        #pragma unroll 8
        for (int o = 0; o < MLP0; ++o) s = fmaf(w2[p * MLP0 + o], w1eff[o * 30 + rc], s);
        wfold[e] = s;
    }
    if (tid < MLP1) {
        float s = b2[tid];
        #pragma unroll 8
        for (int o = 0; o < MLP0; ++o) s = fmaf(w2[tid * MLP0 + o], b1[o], s);
        biasf[tid] = s;
    }
    __syncthreads();

    // ---- stage 1: exact 10-NN, lane-pair per query, interleaved slices ----
    const int s  = tid & 1;            // slice
    const int nq = n0 + (tid >> 1);    // query index
    const float4 qd = cand[nq];
    const float qx = qd.x, qy = qd.y, qz = qd.z;

    // e' = 0.5*|c|^2 - q.c  (monotone in d^2 for fixed q; self is strict min)
    float dist[KK];
    int   idx[KK];
    #pragma unroll
    for (int i = 0; i < KK; ++i) { dist[i] = CUDART_INF_F; idx[i] = 0; }

    for (int m0 = s; m0 < NN; m0 += 16) {
        float e[8];
        #pragma unroll
        for (int u = 0; u < 8; ++u) {
            float4 cc = cand[m0 + 2 * u];
            float t = cc.w;
            t = fmaf(-qx, cc.x, t);
            t = fmaf(-qy, cc.y, t);
            e[u] = fmaf(-qz, cc.z, t);
        }
        // frozen threshold for the whole block: gates are independent FSETPs,
        // no serial dependency on in-block list updates. Stale-threshold
        // inserts are exact: the insert itself compares against the live list.
        const float kth = dist[KK - 1];
        #pragma unroll
        for (int u = 0; u < 8; ++u) {
            if (e[u] < kth) {
                const float v = e[u];
                const int   m = m0 + 2 * u;
                bool c_hi = v < dist[KK - 1];
                #pragma unroll
                for (int i = KK - 1; i >= 1; --i) {
                    bool c_lo = v < dist[i - 1];
                    float tn = c_hi ? v : dist[i];
                    int   ti = c_hi ? m : idx[i];
                    dist[i] = c_lo ? dist[i - 1] : tn;
                    idx[i]  = c_lo ? idx[i - 1]  : ti;
                    c_hi = c_lo;
                }
                dist[0] = c_hi ? v : dist[0];
                idx[0]  = c_hi ? m : idx[0];
            }
        }
    }

    // ---- stage 1b: symmetric pair-merge (snapshot partner, then insert) ----
    float pd[KK]; int pi[KK];
    #pragma unroll
    for (int r = 0; r < KK; ++r) {
        pd[r] = __shfl_xor_sync(0xffffffffu, dist[r], 1);
        pi[r] = __shfl_xor_sync(0xffffffffu, idx[r], 1);
    }
    #pragma unroll
    for (int r = 0; r < KK; ++r) {
        const float v  = pd[r];
        const int   mi = pi[r];
        bool c_hi = (v < dist[KK - 1]) || (v == dist[KK - 1] && mi < idx[KK - 1]);
        #pragma unroll
        for (int i = KK - 1; i >= 1; --i) {
            bool c_lo = (v < dist[i - 1]) || (v == dist[i - 1] && mi < idx[i - 1]);
            float tn = c_hi ? v : dist[i];
            int   ti = c_hi ? mi : idx[i];
            dist[i] = c_lo ? dist[i - 1] : tn;
            idx[i]  = c_lo ? idx[i - 1]  : ti;
            c_hi = c_lo;
        }
        dist[0] = c_hi ? v : dist[0];
        idx[0]  = c_hi ? mi : idx[0];
    }

    // ---- stage 2: gather neighbors + folded matvec (32 outputs per lane) ----
    float nx[KK], ny[KK], nz[KK];
    #pragma unroll
    for (int r = 0; r < KK; ++r) {
        float4 cc = cand[idx[r]];
        nx[r] = cc.x; ny[r] = cc.y; nz[r] = cc.z;
    }

    const int p0 = s * (MLP1 / 2);
    float* op = out + b * (MLP1 * NN) + nq;
    #pragma unroll 4
    for (int pj = 0; pj < MLP1 / 2; ++pj) {
        const int p = p0 + pj;
        float acc = biasf[p];
        const float* wf = wfold + p * 30;
        #pragma unroll
        for (int r = 0; r < KK; ++r) {
            acc = fmaf(wf[r * 3 + 0], nx[r], acc);
            acc = fmaf(wf[r * 3 + 1], ny[r], acc);
            acc = fmaf(wf[r * 3 + 2], nz[r], acc);
        }
        op[p * NN] = acc;
    }
}

extern "C" void kernel_launch(void* const* d_in, const int* in_sizes, int n_in,
                              void* d_out, int out_size)
{
    const float* pos = (const float*)d_in[0];   // (8, 3, 4096)
    const float* w1  = (const float*)d_in[1];   // (64, 12, 2, 2)
    const float* b1  = (const float*)d_in[2];   // (64,)
    const float* w2  = (const float*)d_in[3];   // (64, 64)
    const float* b2  = (const float*)d_in[4];   // (64,)
    float* out = (float*)d_out;                 // (8, 64, 4096)

    cudaFuncSetAttribute(pcms_kernel, cudaFuncAttributeMaxDynamicSharedMemorySize, SMEM_BYTES);

    dim3 grid(NB * (NN / QPB));   // 128 blocks
    dim3 block(TPB);
    pcms_kernel<<<grid, block, SMEM_BYTES>>>(pos, w1, b1, w2, b2, out);
}

// round 4
// speedup vs baseline: 1.7368x; 1.7368x over previous
#include <cuda_runtime.h>
#include <math_constants.h>

#define NB   8
#define NC   3
#define NN   4096
#define KK   10
#define TPB  512          // threads per block (2 per query)
#define QPB  256          // queries per block
#define MLP0 64
#define MLP1 64
#define BUFN 16           // per-lane accept buffer depth

// dynamic smem layout (floats):
//   float4 cand[4096]   : 16384 f
//   float  w1eff[64*30] :  1920 f
//   float  wfold[64*30] :  1920 f
//   float  biasf[64]    :    64 f
//   u64    buf[BUFN*TPB]: 65536 B
#define SMEM_FLOATS (NN*4 + MLP0*30 + MLP1*30 + MLP1)
#define SMEM_BYTES  (SMEM_FLOATS*4 + BUFN*TPB*8)

__global__ __launch_bounds__(TPB, 1)
void pcms_kernel(const float* __restrict__ pos,
                 const float* __restrict__ w1,
                 const float* __restrict__ b1,
                 const float* __restrict__ w2,
                 const float* __restrict__ b2,
                 float* __restrict__ out)
{
    extern __shared__ float smem[];
    float4* cand  = reinterpret_cast<float4*>(smem);
    float*  w1eff = smem + NN * 4;
    float*  wfold = w1eff + MLP0 * 30;
    float*  biasf = wfold + MLP1 * 30;
    unsigned long long* buf =
        reinterpret_cast<unsigned long long*>(smem + SMEM_FLOATS);

    const int tid = threadIdx.x;
    const int b   = blockIdx.x >> 4;          // 16 chunks per batch
    const int n0  = (blockIdx.x & 15) * QPB;

    // ---- stage 0a: candidate table (x, y, z, 0.5*|p|^2) ----
    const float* pb = pos + b * (NC * NN);
    #pragma unroll
    for (int i = 0; i < NN / TPB; ++i) {
        int n = tid + i * TPB;
        float x = pb[n];
        float y = pb[NN + n];
        float z = pb[2 * NN + n];
        cand[n] = make_float4(x, y, z, 0.5f * (x * x + y * y + z * z));
    }

    // ---- stage 0b: fold w1 over the INDS/squeeze mapping -> w1eff[o][r*3+c] ----
    if (tid < MLP0) {
        float acc[30];
        #pragma unroll
        for (int i = 0; i < 30; ++i) acc[i] = 0.f;
        const int STAB[4][2][2] = {
            {{0, 2}, {4, 6}},   // a
            {{3, 5}, {7, 9}},   // d
            {{1, 3}, {5, 7}},   // b
            {{2, 4}, {6, 8}}    // c
        };
        #pragma unroll
        for (int q = 0; q < 4; ++q)
            #pragma unroll
            for (int c = 0; c < 3; ++c)
                #pragma unroll
                for (int i = 0; i < 2; ++i)
                    #pragma unroll
                    for (int j = 0; j < 2; ++j) {
                        int r = STAB[q][i][j];
                        acc[r * 3 + c] += w1[tid * 48 + (q * 3 + c) * 4 + i * 2 + j];
                    }
        #pragma unroll
        for (int i = 0; i < 30; ++i) w1eff[tid * 30 + i] = acc[i];
    }
    __syncthreads();

    // ---- stage 0c: wfold + bias fold ----
    for (int e = tid; e < MLP1 * 30; e += TPB) {
        int p = e / 30, rc = e % 30;
        float s = 0.f;
        #pragma unroll 8
        for (int o = 0; o < MLP0; ++o) s = fmaf(w2[p * MLP0 + o], w1eff[o * 30 + rc], s);
        wfold[e] = s;
    }
    if (tid < MLP1) {
        float s = b2[tid];
        #pragma unroll 8
        for (int o = 0; o < MLP0; ++o) s = fmaf(w2[tid * MLP0 + o], b1[o], s);
        biasf[tid] = s;
    }
    __syncthreads();

    // ---- stage 1: exact 10-NN, lane-pair per query, buffered accepts ----
    const int s  = tid & 1;            // slice
    const int nq = n0 + (tid >> 1);    // query index
    const float4 qd = cand[nq];
    const float qx = qd.x, qy = qd.y, qz = qd.z;

    float dist[KK];
    int   idx[KK];
    #pragma unroll
    for (int i = 0; i < KK; ++i) { dist[i] = CUDART_INF_F; idx[i] = 0; }

    float kth = CUDART_INF_F;
    int bufpos = 0;

    // drain buffered accepts into the sorted list, refresh kth
    auto flush = [&]() {
        int j = 0;
        while (__any_sync(0xffffffffu, j < bufpos)) {
            if (j < bufpos) {
                unsigned long long pk = buf[j * TPB + tid];
                const float v = __int_as_float((int)(pk >> 32));
                const int   m = (int)(pk & 0xffffffffu);
                if (v < dist[KK - 1]) {            // live re-gate (exact)
                    bool c_hi = true;
                    #pragma unroll
                    for (int i = KK - 1; i >= 1; --i) {
                        bool c_lo = v < dist[i - 1];
                        float tn = c_hi ? v : dist[i];
                        int   ti = c_hi ? m : idx[i];
                        dist[i] = c_lo ? dist[i - 1] : tn;
                        idx[i]  = c_lo ? idx[i - 1]  : ti;
                        c_hi = c_lo;
                    }
                    dist[0] = c_hi ? v : dist[0];
                    idx[0]  = c_hi ? m : idx[0];
                }
            }
            ++j;
        }
        bufpos = 0;
        kth = dist[KK - 1];
    };

    for (int m0 = s; m0 < NN; m0 += 16) {
        float e[8];
        #pragma unroll
        for (int u = 0; u < 8; ++u) {
            float4 cc = cand[m0 + 2 * u];
            float t = cc.w;
            t = fmaf(-qx, cc.x, t);
            t = fmaf(-qy, cc.y, t);
            e[u] = fmaf(-qz, cc.z, t);
        }
        // cheap push: pack (e, idx) into u64, store to per-lane smem queue.
        // gate uses the flush-frozen kth -> all 8 FSETPs independent.
        #pragma unroll
        for (int u = 0; u < 8; ++u) {
            if (e[u] < kth) {
                unsigned long long pk =
                    (((unsigned long long)(unsigned)__float_as_int(e[u])) << 32)
                    | (unsigned)(m0 + 2 * u);
                buf[bufpos * TPB + tid] = pk;
                ++bufpos;
            }
        }
        // room check once per block: need 8 free slots for the next block
        if (__any_sync(0xffffffffu, bufpos >= BUFN - 7)) flush();
    }
    flush();   // drain remainder

    // ---- stage 1b: symmetric pair-merge (snapshot partner, then insert) ----
    float pd[KK]; int pi[KK];
    #pragma unroll
    for (int r = 0; r < KK; ++r) {
        pd[r] = __shfl_xor_sync(0xffffffffu, dist[r], 1);
        pi[r] = __shfl_xor_sync(0xffffffffu, idx[r], 1);
    }
    #pragma unroll
    for (int r = 0; r < KK; ++r) {
        const float v  = pd[r];
        const int   mi = pi[r];
        bool c_hi = (v < dist[KK - 1]) || (v == dist[KK - 1] && mi < idx[KK - 1]);
        #pragma unroll
        for (int i = KK - 1; i >= 1; --i) {
            bool c_lo = (v < dist[i - 1]) || (v == dist[i - 1] && mi < idx[i - 1]);
            float tn = c_hi ? v : dist[i];
            int   ti = c_hi ? mi : idx[i];
            dist[i] = c_lo ? dist[i - 1] : tn;
            idx[i]  = c_lo ? idx[i - 1]  : ti;
            c_hi = c_lo;
        }
        dist[0] = c_hi ? v : dist[0];
        idx[0]  = c_hi ? mi : idx[0];
    }

    // ---- stage 2: gather neighbors + folded matvec (32 outputs per lane) ----
    float nx[KK], ny[KK], nz[KK];
    #pragma unroll
    for (int r = 0; r < KK; ++r) {
        float4 cc = cand[idx[r]];
        nx[r] = cc.x; ny[r] = cc.y; nz[r] = cc.z;
    }

    const int p0 = s * (MLP1 / 2);
    float* op = out + b * (MLP1 * NN) + nq;
    #pragma unroll 4
    for (int pj = 0; pj < MLP1 / 2; ++pj) {
        const int p = p0 + pj;
        float acc = biasf[p];
        const float* wf = wfold + p * 30;
        #pragma unroll
        for (int r = 0; r < KK; ++r) {
            acc = fmaf(wf[r * 3 + 0], nx[r], acc);
            acc = fmaf(wf[r * 3 + 1], ny[r], acc);
            acc = fmaf(wf[r * 3 + 2], nz[r], acc);
        }
        op[p * NN] = acc;
    }
}

extern "C" void kernel_launch(void* const* d_in, const int* in_sizes, int n_in,
                              void* d_out, int out_size)
{
    const float* pos = (const float*)d_in[0];   // (8, 3, 4096)
    const float* w1  = (const float*)d_in[1];   // (64, 12, 2, 2)
    const float* b1  = (const float*)d_in[2];   // (64,)
    const float* w2  = (const float*)d_in[3];   // (64, 64)
    const float* b2  = (const float*)d_in[4];   // (64,)
    float* out = (float*)d_out;                 // (8, 64, 4096)

    cudaFuncSetAttribute(pcms_kernel, cudaFuncAttributeMaxDynamicSharedMemorySize, SMEM_BYTES);

    dim3 grid(NB * (NN / QPB));   // 128 blocks
    dim3 block(TPB);
    pcms_kernel<<<grid, block, SMEM_BYTES>>>(pos, w1, b1, w2, b2, out);
}